// round 15
// baseline (speedup 1.0000x reference)
#include <cuda_runtime.h>
#include <cuda_fp16.h>
#include <cstdint>

static constexpr int IN_F  = 4096;
static constexpr int OUT_F = 4096;
static constexpr int BATCH = 4096;

static constexpr int BM = 128;
static constexpr int BN = 128;
static constexpr int KC = 64;                 // k elements per chunk (128 B rows in fp16)
static constexpr int NCH = IN_F / KC;         // 64, compile-time
static constexpr int STAGES = 3;

static constexpr int STG_A = BM * KC * 2;     // 16384 B
static constexpr int STG_B = BN * KC * 2;     // 16384 B
static constexpr int STG   = STG_A + STG_B;   // 32768 B
static constexpr int SMEM_SZ = STAGES * STG;  // 98304 B per CTA -> 2 CTAs/SM

static constexpr int PREP_GROUPS = 4096;          // groups of {w, w, x}
static constexpr int PREP_BLOCKS = 3 * PREP_GROUPS;  // 12288

// ---------------- device scratch (allocation-free rule: __device__ globals) -------------
__device__ __align__(16) __half g_wh[(size_t)OUT_F * IN_F];
__device__ __align__(16) __half g_xh[(size_t)BATCH * IN_F];
__device__ float g_rowsum[BATCH];
__device__ float g_bias[OUT_F];
// statically initialized; atomicMin/Max over identical data is idempotent across replays
__device__ int   g_qmin = 0x7FFFFFFF, g_qmax = 0x80000000;
__device__ float g_s, g_c;
// self-resetting completion ticket (last block resets to 0 -> replay-deterministic)
__device__ unsigned g_ticket = 0;

// ---------------- helpers ---------------------------------------------------------------
__device__ __forceinline__ uint32_t smem_u32(const void* p) {
    uint32_t a;
    asm("{ .reg .u64 t; cvta.to.shared.u64 t, %1; cvt.u32.u64 %0, t; }" : "=r"(a) : "l"(p));
    return a;
}
__device__ __forceinline__ void cp_async16(uint32_t dst, const void* src) {
    asm volatile("cp.async.cg.shared.global [%0], [%1], 16;" :: "r"(dst), "l"(src));
}
__device__ __forceinline__ void cp_commit() {
    asm volatile("cp.async.commit_group;" ::: "memory");
}
__device__ __forceinline__ void cp_wait1() {
    asm volatile("cp.async.wait_group 1;" ::: "memory");
}
__device__ __forceinline__ uint32_t sw128(uint32_t off) {   // 128B-row xor swizzle
    return off ^ ((off >> 3) & 0x70);
}
__device__ __forceinline__ void ldsm4(uint32_t& r0, uint32_t& r1, uint32_t& r2, uint32_t& r3,
                                      uint32_t addr) {
    asm volatile("ldmatrix.sync.aligned.m8n8.x4.shared.b16 {%0,%1,%2,%3}, [%4];"
                 : "=r"(r0), "=r"(r1), "=r"(r2), "=r"(r3) : "r"(addr));
}
__device__ __forceinline__ void mma16816(float* d, const uint32_t* a, const uint32_t* b) {
    asm volatile(
        "mma.sync.aligned.m16n8k16.row.col.f32.f16.f16.f32 "
        "{%0,%1,%2,%3}, {%4,%5,%6,%7}, {%8,%9}, {%0,%1,%2,%3};"
        : "+f"(d[0]), "+f"(d[1]), "+f"(d[2]), "+f"(d[3])
        : "r"(a[0]), "r"(a[1]), "r"(a[2]), "r"(a[3]), "r"(b[0]), "r"(b[1]));
}
__device__ __forceinline__ uint32_t pkh2(__half a, __half b) {
    __half2 t = __halves2half2(a, b);
    return *reinterpret_cast<uint32_t*>(&t);
}

// ---------------- single prep kernel ----------------------------------------------------
// Groups of 3 blocks: {weight, weight, x} interleaved so every SM carries a blend
// of both DRAM streams. The LAST block to finish (atomic ticket) additionally
// computes bias minmax + dequant + global scalars, then resets the ticket.
__global__ __launch_bounds__(256) void k_prep(const int* __restrict__ q,
                                              const float* __restrict__ x,
                                              const int* __restrict__ bq,
                                              const float* __restrict__ wmn,
                                              const float* __restrict__ wmx,
                                              const float* __restrict__ bmn,
                                              const float* __restrict__ bmx) {
    __shared__ int   smn[8], smx[8];
    __shared__ float ss[8];
    __shared__ int   last_flag;
    int tid = threadIdx.x, wid = tid >> 5, lid = tid & 31;
    int grp = blockIdx.x / 3, r = blockIdx.x % 3;

    if (r < 2) {
        // ---- weight prep: int32 -> fp16 (exact for |q|<=128) + global min/max ----
        int w_idx = 2 * grp + r;                          // 0..8191
        size_t base = ((size_t)w_idx * 256 + tid) * 8;
        int4 a = *(const int4*)(q + base);
        int4 b = *(const int4*)(q + base + 4);
        uint4 o;
        o.x = pkh2(__float2half_rn((float)a.x), __float2half_rn((float)a.y));
        o.y = pkh2(__float2half_rn((float)a.z), __float2half_rn((float)a.w));
        o.z = pkh2(__float2half_rn((float)b.x), __float2half_rn((float)b.y));
        o.w = pkh2(__float2half_rn((float)b.z), __float2half_rn((float)b.w));
        *(uint4*)(g_wh + base) = o;

        int mn = min(min(min(a.x, a.y), min(a.z, a.w)), min(min(b.x, b.y), min(b.z, b.w)));
        int mx = max(max(max(a.x, a.y), max(a.z, a.w)), max(max(b.x, b.y), max(b.z, b.w)));
        #pragma unroll
        for (int s = 16; s; s >>= 1) {
            mn = min(mn, __shfl_xor_sync(0xFFFFFFFFu, mn, s));
            mx = max(mx, __shfl_xor_sync(0xFFFFFFFFu, mx, s));
        }
        if (lid == 0) { smn[wid] = mn; smx[wid] = mx; }
        __syncthreads();
        if (tid == 0) {
            int bmn_i = smn[0], bmx_i = smx[0];
            #pragma unroll
            for (int i = 1; i < 8; i++) { bmn_i = min(bmn_i, smn[i]); bmx_i = max(bmx_i, smx[i]); }
            atomicMin(&g_qmin, bmn_i);
            atomicMax(&g_qmax, bmx_i);
        }
    } else {
        // ---- x prep: fp32 -> fp16 (16B stores) + per-row fp32 sum ----
        int row = grp;
        const float* xr = x + (size_t)row * IN_F;
        size_t ro = (size_t)row * IN_F;
        float sum = 0.f;
        #pragma unroll
        for (int it = 0; it < 2; it++) {
            int i = tid * 8 + it * 2048;
            float4 v0 = *(const float4*)(xr + i);
            float4 v1 = *(const float4*)(xr + i + 4);
            sum += (v0.x + v0.y) + (v0.z + v0.w) + (v1.x + v1.y) + (v1.z + v1.w);
            uint4 o;
            o.x = pkh2(__float2half_rn(v0.x), __float2half_rn(v0.y));
            o.y = pkh2(__float2half_rn(v0.z), __float2half_rn(v0.w));
            o.z = pkh2(__float2half_rn(v1.x), __float2half_rn(v1.y));
            o.w = pkh2(__float2half_rn(v1.z), __float2half_rn(v1.w));
            *(uint4*)(g_xh + ro + i) = o;
        }
        #pragma unroll
        for (int s = 16; s; s >>= 1) sum += __shfl_xor_sync(0xFFFFFFFFu, sum, s);
        if (lid == 0) ss[wid] = sum;
        __syncthreads();
        if (tid == 0) {
            float t = ss[0];
            #pragma unroll
            for (int i = 1; i < 8; i++) t += ss[i];
            g_rowsum[row] = t;
        }
    }

    // ---- completion ticket; last block does the bias/scalar tail ----
    if (tid == 0) {
        __threadfence();
        unsigned t = atomicAdd(&g_ticket, 1u);
        last_flag = (t == (unsigned)(PREP_BLOCKS - 1));
    }
    __syncthreads();
    if (last_flag) {
        // all blocks' atomicMin/Max are globally visible (fence before ticket)
        int base4 = tid * 16;                              // 256 * 16 = 4096
        int4 b0 = *(const int4*)(bq + base4);
        int4 b1 = *(const int4*)(bq + base4 + 4);
        int4 b2 = *(const int4*)(bq + base4 + 8);
        int4 b3 = *(const int4*)(bq + base4 + 12);
        int mn = min(min(min(b0.x, b0.y), min(b0.z, b0.w)),
                     min(min(b1.x, b1.y), min(b1.z, b1.w)));
        mn = min(mn, min(min(min(b2.x, b2.y), min(b2.z, b2.w)),
                         min(min(b3.x, b3.y), min(b3.z, b3.w))));
        int mx = max(max(max(b0.x, b0.y), max(b0.z, b0.w)),
                     max(max(b1.x, b1.y), max(b1.z, b1.w)));
        mx = max(mx, max(max(max(b2.x, b2.y), max(b2.z, b2.w)),
                         max(max(b3.x, b3.y), max(b3.z, b3.w))));
        #pragma unroll
        for (int s = 16; s; s >>= 1) {
            mn = min(mn, __shfl_xor_sync(0xFFFFFFFFu, mn, s));
            mx = max(mx, __shfl_xor_sync(0xFFFFFFFFu, mx, s));
        }
        if (lid == 0) { smn[wid] = mn; smx[wid] = mx; }
        __syncthreads();
        __shared__ int bqmin, bqmax;
        if (tid == 0) {
            int bmn_i = smn[0], bmx_i = smx[0];
            #pragma unroll
            for (int i = 1; i < 8; i++) { bmn_i = min(bmn_i, smn[i]); bmx_i = max(bmx_i, smx[i]); }
            bqmin = bmn_i; bqmax = bmx_i;
            int qmin = atomicAdd(&g_qmin, 0), qmax = atomicAdd(&g_qmax, 0);
            float s = (wmx[0] - wmn[0]) / (float)(qmax - qmin);
            g_s = s;
            g_c = wmn[0] - s * (float)qmin;
            g_ticket = 0;                                  // reset for next graph replay
        }
        __syncthreads();
        float bs = (bmx[0] - bmn[0]) / (float)(bqmax - bqmin);
        int q0 = bqmin;
        float bb = bmn[0];
        g_bias[base4 + 0]  = (float)(b0.x - q0) * bs + bb;
        g_bias[base4 + 1]  = (float)(b0.y - q0) * bs + bb;
        g_bias[base4 + 2]  = (float)(b0.z - q0) * bs + bb;
        g_bias[base4 + 3]  = (float)(b0.w - q0) * bs + bb;
        g_bias[base4 + 4]  = (float)(b1.x - q0) * bs + bb;
        g_bias[base4 + 5]  = (float)(b1.y - q0) * bs + bb;
        g_bias[base4 + 6]  = (float)(b1.z - q0) * bs + bb;
        g_bias[base4 + 7]  = (float)(b1.w - q0) * bs + bb;
        g_bias[base4 + 8]  = (float)(b2.x - q0) * bs + bb;
        g_bias[base4 + 9]  = (float)(b2.y - q0) * bs + bb;
        g_bias[base4 + 10] = (float)(b2.z - q0) * bs + bb;
        g_bias[base4 + 11] = (float)(b2.w - q0) * bs + bb;
        g_bias[base4 + 12] = (float)(b3.x - q0) * bs + bb;
        g_bias[base4 + 13] = (float)(b3.y - q0) * bs + bb;
        g_bias[base4 + 14] = (float)(b3.z - q0) * bs + bb;
        g_bias[base4 + 15] = (float)(b3.w - q0) * bs + bb;
    }
}

// ---------------- GEMM (mma.sync fp16, cp.async 3-stage, 2 CTAs/SM, phase-stagger) ------
// CTA 128x128, full K, 1024 CTAs; strength-reduced smem addressing:
//   addr = st + ((base + mt*2048 + kb) ^ swz),  swz = (base>>3)&0x70
// (mt*2048 touches bits>=11; base bits 4-6 <= 16 so +kb<=96 never carries into
//  bit 7; the mask bits 7-9 are invariant under both deltas.)
// Per-warp phase stagger overlaps LDSM-burst and MMA-burst phases across the
// 4 warps on each SMSP. PROVEN-BEST config (R13: 512k cycles) — unchanged.
__global__ __launch_bounds__(256, 2) void k_gemm(float* __restrict__ out) {
    extern __shared__ char sm[];
    uint32_t sb = smem_u32(sm);
    int tid = threadIdx.x, lane = tid & 31, wid = tid >> 5;
    int warp_m = wid >> 2;      // 0..1 (64 rows each)
    int warp_n = wid & 3;       // 0..3 (32 cols each)
    int tile_n = blockIdx.x & 31;
    int tile_m = blockIdx.x >> 5;
    int stagger = (wid + (wid >> 2)) & 3;

    const __half* Abase = g_xh + (size_t)tile_m * BM * IN_F;
    const __half* Bbase = g_wh + (size_t)tile_n * BN * IN_F;

    float acc[4][4][4];
    #pragma unroll
    for (int mt = 0; mt < 4; mt++)
        #pragma unroll
        for (int nt = 0; nt < 4; nt++)
            #pragma unroll
            for (int j = 0; j < 4; j++) acc[mt][nt][j] = 0.f;

    int ls = lane >> 3, lr = lane & 7;
    uint32_t afrag[4][4], bfrag[4][2];

    // per-thread UNSWIZZLED base offsets + XOR masks (loop-invariant)
    uint32_t arow0 = (uint32_t)(warp_m * 64 + ((ls & 1) << 3) + lr);
    uint32_t abase = arow0 * 128 + (uint32_t)(ls >> 1) * 16;
    uint32_t aswz  = (abase >> 3) & 0x70;
    uint32_t brow0 = (uint32_t)(warp_n * 32 + ((ls >> 1) << 3) + lr);
    uint32_t bbase = brow0 * 128 + (uint32_t)(ls & 1) * 16;
    uint32_t bswz  = (bbase >> 3) & 0x70;
    uint32_t crow0 = (uint32_t)(tid >> 3), cc16 = (uint32_t)(tid & 7);
    uint32_t cpdst0 = sw128(crow0 * 128 + cc16 * 16);   // +i*4096/+STG_A are swizzle-safe
    uint32_t cpoff0 = crow0 * IN_F + cc16 * 8;

    // issue 1/4 of chunk c's cp.asyncs (2 x 16B per thread); part is compile-time
    auto issue_part = [&](int c, int part, uint32_t st_ld) {
        if (c < NCH) {
            int k0 = c * KC;
            #pragma unroll
            for (int i2 = 0; i2 < 2; i2++) {
                int i = part * 2 + i2;                    // compile-time 0..7
                const __half* src =
                    (i < 4 ? Abase : Bbase) + cpoff0 + (i & 3) * (32 * IN_F) + k0;
                uint32_t dst = st_ld + cpdst0 + (uint32_t)((i & 3) * 4096)
                               + (i < 4 ? 0u : (uint32_t)STG_A);
                cp_async16(dst, src);
            }
        }
    };

    // prologue: chunks 0,1 into stages 0,1
    #pragma unroll
    for (int c = 0; c < STAGES - 1; c++) {
        #pragma unroll
        for (int p = 0; p < 4; p++) issue_part(c, p, sb + (uint32_t)c * STG);
        cp_commit();
    }

    uint32_t st_use = sb, st_ld = sb + 2 * STG;
    for (int c = 0; c < NCH; c++) {
        cp_wait1();               // chunk c resident (<=1 younger group pending)
        __syncthreads();          // publish all warps' chunk-c writes + drain st_ld reads

        #pragma unroll
        for (int kk0 = 0; kk0 < 4; kk0++) {
            int kk = (kk0 + stagger) & 3;                // per-warp phase rotation
            uint32_t kb = (uint32_t)kk << 5;
            #pragma unroll
            for (int mt = 0; mt < 4; mt++)
                ldsm4(afrag[mt][0], afrag[mt][1], afrag[mt][2], afrag[mt][3],
                      st_use + ((abase + (uint32_t)(mt * 2048) + kb) ^ aswz));
            #pragma unroll
            for (int np = 0; np < 2; np++)
                ldsm4(bfrag[2 * np][0], bfrag[2 * np][1],
                      bfrag[2 * np + 1][0], bfrag[2 * np + 1][1],
                      st_use + (uint32_t)STG_A
                             + ((bbase + (uint32_t)(np * 2048) + kb) ^ bswz));
            issue_part(c + 2, kk0, st_ld);               // spread next-chunk loads
            #pragma unroll
            for (int mt = 0; mt < 4; mt++)
                #pragma unroll
                for (int nt = 0; nt < 4; nt++)
                    mma16816(acc[mt][nt], afrag[mt], bfrag[nt]);
        }
        cp_commit();
        st_use += STG; if (st_use == sb + 3 * STG) st_use = sb;
        st_ld  += STG; if (st_ld  == sb + 3 * STG) st_ld  = sb;
    }

    // epilogue: y = s*acc + c*rowsum[row] + bias[col]
    float s = g_s, cw = g_c;
    int r0 = tile_m * BM + warp_m * 64 + (lane >> 2);
    float rs[4][2];
    #pragma unroll
    for (int mt = 0; mt < 4; mt++) {
        rs[mt][0] = cw * g_rowsum[r0 + mt * 16];
        rs[mt][1] = cw * g_rowsum[r0 + mt * 16 + 8];
    }
    int colbase = tile_n * BN + warp_n * 32 + 2 * (lane & 3);
    #pragma unroll
    for (int mt = 0; mt < 4; mt++) {
        #pragma unroll
        for (int nt = 0; nt < 4; nt++) {
            int col = colbase + nt * 8;
            float b0 = g_bias[col], b1 = g_bias[col + 1];
            int row = r0 + mt * 16;
            float2 v0 = make_float2(fmaf(s, acc[mt][nt][0], rs[mt][0] + b0),
                                    fmaf(s, acc[mt][nt][1], rs[mt][0] + b1));
            *(float2*)(out + (size_t)row * OUT_F + col) = v0;
            float2 v1 = make_float2(fmaf(s, acc[mt][nt][2], rs[mt][1] + b0),
                                    fmaf(s, acc[mt][nt][3], rs[mt][1] + b1));
            *(float2*)(out + (size_t)(row + 8) * OUT_F + col) = v1;
        }
    }
}

// ---------------- launch ----------------------------------------------------------------
extern "C" void kernel_launch(void* const* d_in, const int* in_sizes, int n_in,
                              void* d_out, int out_size) {
    const float* x   = (const float*)d_in[0];
    const int*   wq  = (const int*)d_in[1];
    const int*   bq  = (const int*)d_in[2];
    const float* wmn = (const float*)d_in[3];
    const float* wmx = (const float*)d_in[4];
    const float* bmn = (const float*)d_in[5];
    const float* bmx = (const float*)d_in[6];
    float* out = (float*)d_out;

    k_prep<<<PREP_BLOCKS, 256>>>(wq, x, bq, wmn, wmx, bmn, bmx);

    cudaFuncSetAttribute(k_gemm, cudaFuncAttributeMaxDynamicSharedMemorySize, SMEM_SZ);
    k_gemm<<<(BATCH / BM) * (OUT_F / BN), 256, SMEM_SZ>>>(out);
}

// round 16
// speedup vs baseline: 1.0260x; 1.0260x over previous
#include <cuda_runtime.h>
#include <cuda_fp16.h>
#include <cstdint>

static constexpr int IN_F  = 4096;
static constexpr int OUT_F = 4096;
static constexpr int BATCH = 4096;

static constexpr int BM = 128;
static constexpr int BN = 128;
static constexpr int KC = 64;                 // k elements per chunk (128 B rows in fp16)
static constexpr int NCH = IN_F / KC;         // 64, compile-time
static constexpr int STAGES = 3;

static constexpr int STG_A = BM * KC * 2;     // 16384 B
static constexpr int STG_B = BN * KC * 2;     // 16384 B
static constexpr int STG   = STG_A + STG_B;   // 32768 B
static constexpr int SMEM_SZ = STAGES * STG;  // 98304 B per CTA -> 2 CTAs/SM

static constexpr int PREP_GROUPS = 4096;          // groups of {w, w, x}
static constexpr int PREP_BLOCKS = 3 * PREP_GROUPS;  // 12288

// ---------------- device scratch (allocation-free rule: __device__ globals) -------------
__device__ __align__(16) __half g_wh[(size_t)OUT_F * IN_F];
__device__ __align__(16) __half g_xh[(size_t)BATCH * IN_F];
__device__ float g_rowsum[BATCH];
__device__ float g_bias[OUT_F];
// statically initialized; atomicMin/Max over identical data is idempotent across replays
__device__ int   g_qmin = 0x7FFFFFFF, g_qmax = 0x80000000;
__device__ float g_s, g_c;

// ---------------- helpers ---------------------------------------------------------------
__device__ __forceinline__ uint32_t smem_u32(const void* p) {
    uint32_t a;
    asm("{ .reg .u64 t; cvta.to.shared.u64 t, %1; cvt.u32.u64 %0, t; }" : "=r"(a) : "l"(p));
    return a;
}
__device__ __forceinline__ void cp_async16(uint32_t dst, const void* src) {
    asm volatile("cp.async.cg.shared.global [%0], [%1], 16;" :: "r"(dst), "l"(src));
}
__device__ __forceinline__ void cp_commit() {
    asm volatile("cp.async.commit_group;" ::: "memory");
}
__device__ __forceinline__ void cp_wait1() {
    asm volatile("cp.async.wait_group 1;" ::: "memory");
}
__device__ __forceinline__ uint32_t sw128(uint32_t off) {   // 128B-row xor swizzle
    return off ^ ((off >> 3) & 0x70);
}
__device__ __forceinline__ void ldsm4(uint32_t& r0, uint32_t& r1, uint32_t& r2, uint32_t& r3,
                                      uint32_t addr) {
    asm volatile("ldmatrix.sync.aligned.m8n8.x4.shared.b16 {%0,%1,%2,%3}, [%4];"
                 : "=r"(r0), "=r"(r1), "=r"(r2), "=r"(r3) : "r"(addr));
}
__device__ __forceinline__ void mma16816(float* d, const uint32_t* a, const uint32_t* b) {
    asm volatile(
        "mma.sync.aligned.m16n8k16.row.col.f32.f16.f16.f32 "
        "{%0,%1,%2,%3}, {%4,%5,%6,%7}, {%8,%9}, {%0,%1,%2,%3};"
        : "+f"(d[0]), "+f"(d[1]), "+f"(d[2]), "+f"(d[3])
        : "r"(a[0]), "r"(a[1]), "r"(a[2]), "r"(a[3]), "r"(b[0]), "r"(b[1]));
}
__device__ __forceinline__ uint32_t pkh2(__half a, __half b) {
    __half2 t = __halves2half2(a, b);
    return *reinterpret_cast<uint32_t*>(&t);
}

// ---------------- merged prep kernel ----------------------------------------------------
// Groups of 3 blocks: {weight, weight, x} interleaved so every SM carries a blend
// of the int-read and float-read DRAM streams. No grid-wide tail (the R15
// last-block-done fold serialized bias behind a full drain and regressed).
__global__ __launch_bounds__(256) void k_prep(const int* __restrict__ q,
                                              const float* __restrict__ x) {
    __shared__ int   smn[8], smx[8];
    __shared__ float ss[8];
    int tid = threadIdx.x, wid = tid >> 5, lid = tid & 31;
    int grp = blockIdx.x / 3, r = blockIdx.x % 3;

    if (r < 2) {
        // ---- weight prep: int32 -> fp16 (exact for |q|<=128) + global min/max ----
        int w_idx = 2 * grp + r;                          // 0..8191
        size_t base = ((size_t)w_idx * 256 + tid) * 8;
        int4 a = *(const int4*)(q + base);
        int4 b = *(const int4*)(q + base + 4);
        uint4 o;
        o.x = pkh2(__float2half_rn((float)a.x), __float2half_rn((float)a.y));
        o.y = pkh2(__float2half_rn((float)a.z), __float2half_rn((float)a.w));
        o.z = pkh2(__float2half_rn((float)b.x), __float2half_rn((float)b.y));
        o.w = pkh2(__float2half_rn((float)b.z), __float2half_rn((float)b.w));
        *(uint4*)(g_wh + base) = o;

        int mn = min(min(min(a.x, a.y), min(a.z, a.w)), min(min(b.x, b.y), min(b.z, b.w)));
        int mx = max(max(max(a.x, a.y), max(a.z, a.w)), max(max(b.x, b.y), max(b.z, b.w)));
        #pragma unroll
        for (int s = 16; s; s >>= 1) {
            mn = min(mn, __shfl_xor_sync(0xFFFFFFFFu, mn, s));
            mx = max(mx, __shfl_xor_sync(0xFFFFFFFFu, mx, s));
        }
        if (lid == 0) { smn[wid] = mn; smx[wid] = mx; }
        __syncthreads();
        if (tid == 0) {
            int bmn_i = smn[0], bmx_i = smx[0];
            #pragma unroll
            for (int i = 1; i < 8; i++) { bmn_i = min(bmn_i, smn[i]); bmx_i = max(bmx_i, smx[i]); }
            atomicMin(&g_qmin, bmn_i);
            atomicMax(&g_qmax, bmx_i);
        }
    } else {
        // ---- x prep: fp32 -> fp16 (16B stores) + per-row fp32 sum ----
        int row = grp;
        const float* xr = x + (size_t)row * IN_F;
        size_t ro = (size_t)row * IN_F;
        float sum = 0.f;
        #pragma unroll
        for (int it = 0; it < 2; it++) {
            int i = tid * 8 + it * 2048;
            float4 v0 = *(const float4*)(xr + i);
            float4 v1 = *(const float4*)(xr + i + 4);
            sum += (v0.x + v0.y) + (v0.z + v0.w) + (v1.x + v1.y) + (v1.z + v1.w);
            uint4 o;
            o.x = pkh2(__float2half_rn(v0.x), __float2half_rn(v0.y));
            o.y = pkh2(__float2half_rn(v0.z), __float2half_rn(v0.w));
            o.z = pkh2(__float2half_rn(v1.x), __float2half_rn(v1.y));
            o.w = pkh2(__float2half_rn(v1.z), __float2half_rn(v1.w));
            *(uint4*)(g_xh + ro + i) = o;
        }
        #pragma unroll
        for (int s = 16; s; s >>= 1) sum += __shfl_xor_sync(0xFFFFFFFFu, sum, s);
        if (lid == 0) ss[wid] = sum;
        __syncthreads();
        if (tid == 0) {
            float t = ss[0];
            #pragma unroll
            for (int i = 1; i < 8; i++) t += ss[i];
            g_rowsum[row] = t;
        }
    }
}

// bias: minmax + dequant + global scalars (runs after k_prep).  1 block x 1024
__global__ __launch_bounds__(1024) void k_bias(const int* __restrict__ bq,
                                               const float* __restrict__ wmn,
                                               const float* __restrict__ wmx,
                                               const float* __restrict__ bmn,
                                               const float* __restrict__ bmx) {
    int base = threadIdx.x * 4;
    int4 a = *(const int4*)(bq + base);
    int mn = min(min(a.x, a.y), min(a.z, a.w));
    int mx = max(max(a.x, a.y), max(a.z, a.w));
    #pragma unroll
    for (int s = 16; s; s >>= 1) {
        mn = min(mn, __shfl_xor_sync(0xFFFFFFFFu, mn, s));
        mx = max(mx, __shfl_xor_sync(0xFFFFFFFFu, mx, s));
    }
    __shared__ int smn[32], smx[32];
    __shared__ int bqmin, bqmax;
    int wid = threadIdx.x >> 5, lid = threadIdx.x & 31;
    if (lid == 0) { smn[wid] = mn; smx[wid] = mx; }
    __syncthreads();
    if (threadIdx.x == 0) {
        int bmn_i = smn[0], bmx_i = smx[0];
        #pragma unroll
        for (int i = 1; i < 32; i++) { bmn_i = min(bmn_i, smn[i]); bmx_i = max(bmx_i, smx[i]); }
        bqmin = bmn_i; bqmax = bmx_i;
        float s = (wmx[0] - wmn[0]) / (float)(g_qmax - g_qmin);
        g_s = s;
        g_c = wmn[0] - s * (float)g_qmin;
    }
    __syncthreads();
    float bs = (bmx[0] - bmn[0]) / (float)(bqmax - bqmin);
    int q0 = bqmin;
    float b0 = bmn[0];
    g_bias[base + 0] = (float)(a.x - q0) * bs + b0;
    g_bias[base + 1] = (float)(a.y - q0) * bs + b0;
    g_bias[base + 2] = (float)(a.z - q0) * bs + b0;
    g_bias[base + 3] = (float)(a.w - q0) * bs + b0;
}

// ---------------- GEMM (mma.sync fp16, cp.async 3-stage, 2 CTAs/SM, phase-stagger) ------
// CTA 128x128, full K, 1024 CTAs; strength-reduced smem addressing:
//   addr = st + ((base + mt*2048 + kb) ^ swz),  swz = (base>>3)&0x70
// (mt*2048 touches bits>=11; base bits 4-6 <= 16 so +kb<=96 never carries into
//  bit 7; the mask bits 7-9 are invariant under both deltas.)
// Per-warp phase stagger overlaps LDSM-burst and MMA-burst phases across the
// 4 warps on each SMSP. PROVEN-BEST config (R13-R15: 512k cycles) — unchanged.
__global__ __launch_bounds__(256, 2) void k_gemm(float* __restrict__ out) {
    extern __shared__ char sm[];
    uint32_t sb = smem_u32(sm);
    int tid = threadIdx.x, lane = tid & 31, wid = tid >> 5;
    int warp_m = wid >> 2;      // 0..1 (64 rows each)
    int warp_n = wid & 3;       // 0..3 (32 cols each)
    int tile_n = blockIdx.x & 31;
    int tile_m = blockIdx.x >> 5;
    int stagger = (wid + (wid >> 2)) & 3;

    const __half* Abase = g_xh + (size_t)tile_m * BM * IN_F;
    const __half* Bbase = g_wh + (size_t)tile_n * BN * IN_F;

    float acc[4][4][4];
    #pragma unroll
    for (int mt = 0; mt < 4; mt++)
        #pragma unroll
        for (int nt = 0; nt < 4; nt++)
            #pragma unroll
            for (int j = 0; j < 4; j++) acc[mt][nt][j] = 0.f;

    int ls = lane >> 3, lr = lane & 7;
    uint32_t afrag[4][4], bfrag[4][2];

    // per-thread UNSWIZZLED base offsets + XOR masks (loop-invariant)
    uint32_t arow0 = (uint32_t)(warp_m * 64 + ((ls & 1) << 3) + lr);
    uint32_t abase = arow0 * 128 + (uint32_t)(ls >> 1) * 16;
    uint32_t aswz  = (abase >> 3) & 0x70;
    uint32_t brow0 = (uint32_t)(warp_n * 32 + ((ls >> 1) << 3) + lr);
    uint32_t bbase = brow0 * 128 + (uint32_t)(ls & 1) * 16;
    uint32_t bswz  = (bbase >> 3) & 0x70;
    uint32_t crow0 = (uint32_t)(tid >> 3), cc16 = (uint32_t)(tid & 7);
    uint32_t cpdst0 = sw128(crow0 * 128 + cc16 * 16);   // +i*4096/+STG_A are swizzle-safe
    uint32_t cpoff0 = crow0 * IN_F + cc16 * 8;

    // issue 1/4 of chunk c's cp.asyncs (2 x 16B per thread); part is compile-time
    auto issue_part = [&](int c, int part, uint32_t st_ld) {
        if (c < NCH) {
            int k0 = c * KC;
            #pragma unroll
            for (int i2 = 0; i2 < 2; i2++) {
                int i = part * 2 + i2;                    // compile-time 0..7
                const __half* src =
                    (i < 4 ? Abase : Bbase) + cpoff0 + (i & 3) * (32 * IN_F) + k0;
                uint32_t dst = st_ld + cpdst0 + (uint32_t)((i & 3) * 4096)
                               + (i < 4 ? 0u : (uint32_t)STG_A);
                cp_async16(dst, src);
            }
        }
    };

    // prologue: chunks 0,1 into stages 0,1
    #pragma unroll
    for (int c = 0; c < STAGES - 1; c++) {
        #pragma unroll
        for (int p = 0; p < 4; p++) issue_part(c, p, sb + (uint32_t)c * STG);
        cp_commit();
    }

    uint32_t st_use = sb, st_ld = sb + 2 * STG;
    for (int c = 0; c < NCH; c++) {
        cp_wait1();               // chunk c resident (<=1 younger group pending)
        __syncthreads();          // publish all warps' chunk-c writes + drain st_ld reads

        #pragma unroll
        for (int kk0 = 0; kk0 < 4; kk0++) {
            int kk = (kk0 + stagger) & 3;                // per-warp phase rotation
            uint32_t kb = (uint32_t)kk << 5;
            #pragma unroll
            for (int mt = 0; mt < 4; mt++)
                ldsm4(afrag[mt][0], afrag[mt][1], afrag[mt][2], afrag[mt][3],
                      st_use + ((abase + (uint32_t)(mt * 2048) + kb) ^ aswz));
            #pragma unroll
            for (int np = 0; np < 2; np++)
                ldsm4(bfrag[2 * np][0], bfrag[2 * np][1],
                      bfrag[2 * np + 1][0], bfrag[2 * np + 1][1],
                      st_use + (uint32_t)STG_A
                             + ((bbase + (uint32_t)(np * 2048) + kb) ^ bswz));
            issue_part(c + 2, kk0, st_ld);               // spread next-chunk loads
            #pragma unroll
            for (int mt = 0; mt < 4; mt++)
                #pragma unroll
                for (int nt = 0; nt < 4; nt++)
                    mma16816(acc[mt][nt], afrag[mt], bfrag[nt]);
        }
        cp_commit();
        st_use += STG; if (st_use == sb + 3 * STG) st_use = sb;
        st_ld  += STG; if (st_ld  == sb + 3 * STG) st_ld  = sb;
    }

    // epilogue: y = s*acc + c*rowsum[row] + bias[col]
    float s = g_s, cw = g_c;
    int r0 = tile_m * BM + warp_m * 64 + (lane >> 2);
    float rs[4][2];
    #pragma unroll
    for (int mt = 0; mt < 4; mt++) {
        rs[mt][0] = cw * g_rowsum[r0 + mt * 16];
        rs[mt][1] = cw * g_rowsum[r0 + mt * 16 + 8];
    }
    int colbase = tile_n * BN + warp_n * 32 + 2 * (lane & 3);
    #pragma unroll
    for (int mt = 0; mt < 4; mt++) {
        #pragma unroll
        for (int nt = 0; nt < 4; nt++) {
            int col = colbase + nt * 8;
            float b0 = g_bias[col], b1 = g_bias[col + 1];
            int row = r0 + mt * 16;
            float2 v0 = make_float2(fmaf(s, acc[mt][nt][0], rs[mt][0] + b0),
                                    fmaf(s, acc[mt][nt][1], rs[mt][0] + b1));
            *(float2*)(out + (size_t)row * OUT_F + col) = v0;
            float2 v1 = make_float2(fmaf(s, acc[mt][nt][2], rs[mt][1] + b0),
                                    fmaf(s, acc[mt][nt][3], rs[mt][1] + b1));
            *(float2*)(out + (size_t)(row + 8) * OUT_F + col) = v1;
        }
    }
}

// ---------------- launch ----------------------------------------------------------------
extern "C" void kernel_launch(void* const* d_in, const int* in_sizes, int n_in,
                              void* d_out, int out_size) {
    const float* x   = (const float*)d_in[0];
    const int*   wq  = (const int*)d_in[1];
    const int*   bq  = (const int*)d_in[2];
    const float* wmn = (const float*)d_in[3];
    const float* wmx = (const float*)d_in[4];
    const float* bmn = (const float*)d_in[5];
    const float* bmx = (const float*)d_in[6];
    float* out = (float*)d_out;

    k_prep<<<PREP_BLOCKS, 256>>>(wq, x);
    k_bias<<<1, 1024>>>(bq, wmn, wmx, bmn, bmx);

    cudaFuncSetAttribute(k_gemm, cudaFuncAttributeMaxDynamicSharedMemorySize, SMEM_SZ);
    k_gemm<<<(BATCH / BM) * (OUT_F / BN), 256, SMEM_SZ>>>(out);
}